// round 13
// baseline (speedup 1.0000x reference)
#include <cuda_runtime.h>
#include <cuda_bf16.h>
#include <math.h>

// Problem shape (fixed): B=64, T=1024, I=256, H=1024, P=10
// Output depends only on batch sample 63 (h[-1]); LSTM recurrence is
// independent per batch row, so we compute only sample 63's trajectory.
//
// Sync design: NO global barrier. Each h value is published as an fp32 whose
// LOW 2 MANTISSA BITS carry an epoch tag ((t>>2)&3); buffers rotate over
// NBUF=4 slots (slot = t&3). Slot+epoch disambiguates occupants (prior
// occupant is 4 steps older => different epoch; inter-CTA skew is bounded
// by ~1 step by the dataflow itself). Perturbation from the stolen bits is
// <= 3 ulp per publish and consistent everywhere.
//
// R13 deltas vs R12: (a) publish via 8 direct st.relaxed.gpu.b32 from lanes
// 0..7 -- restores the R9 reducer tail (R12 added ~60cyc of shfl+packing);
// (b) consumer poll is two-slot pipelined (second probe always in flight)
// -- detection lag and max-over-warps spin-phase skew drop ~2x, at exactly
// R9's measured-good probe traffic (16 sectors/warp-iter).

#define T_STEPS 1024
#define IDIM    256
#define HDIM    1024
#define PDIM    10

#define REC_CTAS    128   // CTA c owns h-cols [8c, 8c+8) -> 32 gate columns
#define REC_THREADS 544   // warp 0 = reducer; warps 1..16 = GEMV producers
#define NBUF        4

typedef unsigned long long u64;

// Scratch (static device globals; no allocation allowed)
__device__ float g_xproj[T_STEPS * 4 * HDIM];               // [t][gate][h], bias folded
__device__ __align__(256) unsigned g_hbuf[NBUF][HDIM];      // fp32 bits, low2 = epoch tag

// ---------------------------------------------------------------------------
// PTX helpers
// ---------------------------------------------------------------------------
__device__ __forceinline__ u64 ld_relaxed_gpu64(const u64* p) {
    u64 v;
    asm volatile("ld.relaxed.gpu.b64 %0, [%1];" : "=l"(v) : "l"(p) : "memory");
    return v;
}
__device__ __forceinline__ unsigned ld_relaxed_gpu32(const unsigned* p) {
    unsigned v;
    asm volatile("ld.relaxed.gpu.b32 %0, [%1];" : "=r"(v) : "l"(p) : "memory");
    return v;
}
__device__ __forceinline__ void st_relaxed_gpu32(unsigned* p, unsigned v) {
    asm volatile("st.relaxed.gpu.b32 [%0], %1;" :: "l"(p), "r"(v) : "memory");
}
__device__ __forceinline__ u64 ffma2(u64 a, u64 b, u64 c) {
    u64 d;
    asm("fma.rn.f32x2 %0, %1, %2, %3;" : "=l"(d) : "l"(a), "l"(b), "l"(c));
    return d;
}
__device__ __forceinline__ u64 pack2(float lo, float hi) {
    u64 d;
    asm("mov.b64 %0, {%1, %2};" : "=l"(d) : "f"(lo), "f"(hi));
    return d;
}
__device__ __forceinline__ float2 unpack2(u64 v) {
    float lo, hi;
    asm("mov.b64 {%0, %1}, %2;" : "=f"(lo), "=f"(hi) : "l"(v));
    return make_float2(lo, hi);
}
__device__ __forceinline__ void bar_sync_named(int id, int cnt) {
    asm volatile("bar.sync %0, %1;" :: "r"(id), "r"(cnt) : "memory");
}
__device__ __forceinline__ void bar_arrive_named(int id, int cnt) {
    asm volatile("bar.arrive %0, %1;" :: "r"(id), "r"(cnt) : "memory");
}
// tanh via MUFU: 1 - 2/(exp(2x)+1). Saturates correctly for |x| large.
__device__ __forceinline__ float fast_tanh(float x) {
    return 1.f - __fdividef(2.f, __expf(2.f * x) + 1.f);
}

// ---------------------------------------------------------------------------
// Kernel 0: init h buffers. Slot 0 = fp32 0.0 with tag 0 (the h(0) state);
// slots 1..3 = tag 3 (epoch -1) so step-1..3 consumers spin until the real
// publish (h(1..3) carry epoch tag 0, distinct from 3).
// ---------------------------------------------------------------------------
__global__ void init_kernel() {
    const int i = blockIdx.x * blockDim.x + threadIdx.x;   // 0..NBUF*HDIM-1
    if (i < NBUF * HDIM)
        (&g_hbuf[0][0])[i] = (i < HDIM) ? 0u : 3u;
}

// ---------------------------------------------------------------------------
// Kernel 1: x_proj[t][gate][h] = b_gate[h] + sum_i x[63,t,i] * Wgate_x[i,h]
// ---------------------------------------------------------------------------
__global__ __launch_bounds__(256) void xproj_kernel(
    const float* __restrict__ x,
    const float* __restrict__ Wfx, const float* __restrict__ bf,
    const float* __restrict__ Wix, const float* __restrict__ bi,
    const float* __restrict__ Wgx, const float* __restrict__ bg,
    const float* __restrict__ Wox, const float* __restrict__ bo)
{
    __shared__ float xs[32][IDIM];   // 32 KB

    const float* x63 = x + (size_t)63 * T_STEPS * IDIM;
    const int tid    = threadIdx.x;
    const int cc     = blockIdx.x;             // 0..15
    const int tchunk = blockIdx.y;             // 0..31
    const int gate   = cc >> 2;                // f=0, i=1, g=2, o=3
    const int col    = ((cc & 3) << 8) + tid;  // h-column within gate

    const float* W;
    const float* b;
    if      (gate == 0) { W = Wfx; b = bf; }
    else if (gate == 1) { W = Wix; b = bi; }
    else if (gate == 2) { W = Wgx; b = bg; }
    else                { W = Wox; b = bo; }

    #pragma unroll 4
    for (int k = 0; k < 32; k++)
        xs[k][tid] = x63[(size_t)(tchunk * 32 + k) * IDIM + tid];
    __syncthreads();

    float acc[32];
    #pragma unroll
    for (int t = 0; t < 32; t++) acc[t] = 0.f;

    for (int i = 0; i < IDIM; i++) {
        float wv = __ldg(&W[(size_t)i * HDIM + col]);
        #pragma unroll
        for (int t = 0; t < 32; t++)
            acc[t] = fmaf(xs[t][i], wv, acc[t]);
    }

    const float bias = __ldg(&b[col]);
    #pragma unroll
    for (int t = 0; t < 32; t++)
        g_xproj[(size_t)(tchunk * 32 + t) * 4096 + gate * HDIM + col] = acc[t] + bias;
}

// ---------------------------------------------------------------------------
// Kernel 2: persistent recurrence, 1024 steps, tag-in-mantissa polling.
// Warps 1..16: warp w consumes h rows [64(w-1), 64w): two-slot pipelined
//   b64 poll (one load covers the slice; a second probe always in flight),
//   stage to smem, 32 packed f32x2 FMAs against register-resident weight
//   pairs, one partial, bar.arrive.
// Warp 0: prefetches xproj (hidden under bar wait), bar.sync, treed 16->1
//   reduce, sigmoid gates, cell update + fast tanh, lanes 0..7 publish the
//   8 tagged h values directly (one 32b relaxed store each, 1 sector).
// partial[] is single-buffered: producers cannot write step-(t+1) partials
// until warp 0 published h(t+1), which follows its step-t reduce.
// ---------------------------------------------------------------------------
__global__ __launch_bounds__(REC_THREADS, 1) void rec_kernel(
    const float* __restrict__ Wfh, const float* __restrict__ Wih,
    const float* __restrict__ Wgh, const float* __restrict__ Woh,
    const float* __restrict__ Wph, const float* __restrict__ bp,
    float* __restrict__ out)
{
    __shared__ __align__(16) u64 hs64[16][32];   // per-producer-warp h slice
    __shared__ float partial[16][33];            // [producer][gate-col]

    const int tid  = threadIdx.x;
    const int w    = tid >> 5;
    const int lane = tid & 31;
    const int c    = blockIdx.x;

    const int gate = lane >> 3;
    const int hh   = lane & 7;
    const int hcol = c * 8 + hh;

    if (w == 0) {
        // ---------------- Reducer warp ----------------
        float Creg = 0.f;  // lanes 0..7 hold C for h-cols [8c, 8c+8)
        const float* xpp = &g_xproj[(size_t)gate * HDIM + hcol];

        for (int t = 0; t < T_STEPS; t++) {
            const float xp = __ldg(xpp + (size_t)t * 4096);  // hidden by bar wait
            bar_sync_named(1 + (t & 1), REC_THREADS);

            // Treed 16 -> 1 reduction of producer partials
            float p0 = partial[ 0][lane], p1 = partial[ 1][lane];
            float p2 = partial[ 2][lane], p3 = partial[ 3][lane];
            float p4 = partial[ 4][lane], p5 = partial[ 5][lane];
            float p6 = partial[ 6][lane], p7 = partial[ 7][lane];
            float p8 = partial[ 8][lane], p9 = partial[ 9][lane];
            float pa = partial[10][lane], pb = partial[11][lane];
            float pc = partial[12][lane], pd = partial[13][lane];
            float pe = partial[14][lane], pf = partial[15][lane];
            float s = (((p0 + p1) + (p2 + p3)) + ((p4 + p5) + (p6 + p7)))
                    + (((p8 + p9) + (pa + pb)) + ((pc + pd) + (pe + pf)))
                    + xp;

            // All four gates are sigmoid (per reference)
            const float sg = __fdividef(1.f, 1.f + __expf(-s));
            const float iv = __shfl_sync(0xffffffffu, sg,  8 + hh);
            const float gv = __shfl_sync(0xffffffffu, sg, 16 + hh);
            const float ov = __shfl_sync(0xffffffffu, sg, 24 + hh);
            if (lane < 8) {
                Creg = fmaf(Creg, sg, gv * iv);          // C = C*f + g*i
                const float hn = ov * fast_tanh(Creg);   // h = o*tanh(C)
                // Embed epoch tag ((t+1)>>2)&3 in the low 2 mantissa bits.
                const unsigned hbits = (__float_as_uint(hn) & ~3u)
                                     | ((unsigned)((t + 1) >> 2) & 3u);
                st_relaxed_gpu32(&g_hbuf[(t + 1) & (NBUF - 1)][hcol], hbits);
            }
        }
    } else {
        // ---------------- Producer warps 1..16 ----------------
        const int pw = w - 1;                 // producer index 0..15
        const float* Wp = (gate == 0) ? Wfh : (gate == 1) ? Wih
                        : (gate == 2) ? Wgh : Woh;

        // Register-resident weight pairs for rows [64*pw, 64*pw+64)
        u64 W2[32];
        {
            const float* base = Wp + (size_t)(pw * 64) * HDIM + hcol;
            #pragma unroll
            for (int j = 0; j < 32; j++)
                W2[j] = pack2(base[(size_t)(2 * j) * HDIM],
                              base[(size_t)(2 * j + 1) * HDIM]);
        }

        const int base = pw * 64;             // this warp's h slice base (fp32)

        for (int t = 0; t < T_STEPS; t++) {
            // Two-slot pipelined packed poll: one b64 load per lane covers
            // the whole 64-float slice (8 sectors); a second probe is
            // always in flight, so detection lag and spin-phase skew are
            // ~halved at R9's total probe traffic.
            const u64* hin = (const u64*)&g_hbuf[t & (NBUF - 1)][base];
            const unsigned et = (unsigned)(t >> 2) & 3u;
            u64 v = ld_relaxed_gpu64(&hin[lane]);
            u64 y = ld_relaxed_gpu64(&hin[lane]);
            while ((((unsigned)v) & 3u) != et ||
                   (((unsigned)(v >> 32)) & 3u) != et) {
                v = y;
                y = ld_relaxed_gpu64(&hin[lane]);
            }
            hs64[pw][lane] = v;               // tagged values used as-is
            __syncwarp();

            // GEMV partial: 64 rows x 1 gate-column, packed f32x2
            const ulonglong2* hp = reinterpret_cast<const ulonglong2*>(hs64[pw]);
            u64 acc0 = 0, acc1 = 0, acc2 = 0, acc3 = 0;  // {0.f, 0.f} bits
            #pragma unroll
            for (int k = 0; k < 8; k++) {
                ulonglong2 ha = hp[2 * k];
                ulonglong2 hb = hp[2 * k + 1];
                acc0 = ffma2(W2[4 * k + 0], ha.x, acc0);
                acc1 = ffma2(W2[4 * k + 1], ha.y, acc1);
                acc2 = ffma2(W2[4 * k + 2], hb.x, acc2);
                acc3 = ffma2(W2[4 * k + 3], hb.y, acc3);
            }
            float2 f0 = unpack2(acc0), f1 = unpack2(acc1);
            float2 f2 = unpack2(acc2), f3 = unpack2(acc3);
            partial[pw][lane] =
                ((f0.x + f0.y) + (f1.x + f1.y)) + ((f2.x + f2.y) + (f3.x + f3.y));

            __threadfence_block();                       // order partial write
            bar_arrive_named(1 + (t & 1), REC_THREADS);  // non-blocking
        }
    }

    // Head: y[p] = bp[p] + sum_h h_final[h] * Wph[h][p]   (CTA 0 only)
    // h(1024) lives in slot 0 with epoch tag 0; the previous occupant
    // h(1020) carried tag 3, so the poll is unambiguous.
    if (c == 0 && tid < 32 * PDIM) {
        const unsigned* hf = g_hbuf[T_STEPS & (NBUF - 1)];
        const unsigned etf = (unsigned)(T_STEPS >> 2) & 3u;
        const int p = tid >> 5;
        float acc = 0.f;
        for (int k = lane; k < HDIM; k += 32) {
            unsigned v = ld_relaxed_gpu32(&hf[k]);
            while ((v & 3u) != etf) v = ld_relaxed_gpu32(&hf[k]);
            acc = fmaf(__uint_as_float(v),
                       __ldg(&Wph[(size_t)k * PDIM + p]), acc);
        }
        #pragma unroll
        for (int off = 16; off; off >>= 1)
            acc += __shfl_down_sync(0xffffffffu, acc, off);
        if (lane == 0) out[p] = acc + __ldg(&bp[p]);
    }
}

// ---------------------------------------------------------------------------
extern "C" void kernel_launch(void* const* d_in, const int* in_sizes, int n_in,
                              void* d_out, int out_size)
{
    const float* x   = (const float*)d_in[0];
    const float* Wfx = (const float*)d_in[1];
    const float* Wfh = (const float*)d_in[2];
    const float* bf  = (const float*)d_in[3];
    const float* Wix = (const float*)d_in[4];
    const float* Wih = (const float*)d_in[5];
    const float* bi  = (const float*)d_in[6];
    const float* Wgx = (const float*)d_in[7];
    const float* Wgh = (const float*)d_in[8];
    const float* bg  = (const float*)d_in[9];
    const float* Wox = (const float*)d_in[10];
    const float* Woh = (const float*)d_in[11];
    const float* bo  = (const float*)d_in[12];
    const float* Wph = (const float*)d_in[13];
    const float* bp  = (const float*)d_in[14];
    float* out = (float*)d_out;

    init_kernel<<<4, 1024>>>();
    xproj_kernel<<<dim3(16, 32), 256>>>(x, Wfx, bf, Wix, bi, Wgx, bg, Wox, bo);
    rec_kernel<<<REC_CTAS, REC_THREADS>>>(Wfh, Wih, Wgh, Woh, Wph, bp, out);
}

// round 14
// speedup vs baseline: 1.2277x; 1.2277x over previous
#include <cuda_runtime.h>
#include <cuda_bf16.h>
#include <math.h>

// Problem shape (fixed): B=64, T=1024, I=256, H=1024, P=10
// Output depends only on batch sample 63 (h[-1]); LSTM recurrence is
// independent per batch row, so we compute only sample 63's trajectory.
//
// Sync design: NO global barrier. Each h value is an 8-byte {tag=step, value}
// word published with st.relaxed.gpu.b64 and consumed by polling
// ld.relaxed.gpu.b64 until the tag matches. 8B relaxed atomicity makes
// tag+value indivisible; no fences needed. Buffers rotate over NBUF=4 slots.
//
// R14 = R9 (the 1174us best) with ONE change: the producer-side
// __threadfence_block() before bar.arrive is removed. bar.arrive has
// release semantics on the named barrier in the PTX memory model (the
// documented producer/consumer named-barrier idiom), so the partial[] smem
// store is ordered before the reducer's post-bar.sync loads without the
// ~70-cycle MEMBAR on the producer critical path.
//
// Poll-design journal (measured): dependent single-probe spinning is
// optimal. Two-slot pipelined probes regressed twice (+15%, +23%) -- extra
// in-flight probes stack the per-SM L1tex wavefront FIFO and delay the
// detection load itself. Unit-stride coalesced probes (this layout) beat
// 16B-stride by 7%. Mirrors and packed tag-in-mantissa were neutral.

#define T_STEPS 1024
#define IDIM    256
#define HDIM    1024
#define PDIM    10

#define REC_CTAS    128   // CTA c owns h-cols [8c, 8c+8) -> 32 gate columns
#define REC_THREADS 544   // warp 0 = reducer; warps 1..16 = GEMV producers
#define NBUF        4

typedef unsigned long long u64;

// Scratch (static device globals; no allocation allowed)
__device__ float g_xproj[T_STEPS * 4 * HDIM];            // [t][gate][h], bias folded
__device__ __align__(256) u64 g_hbuf[NBUF][HDIM];        // {tag<<32 | f32 bits(h)}

// ---------------------------------------------------------------------------
// PTX helpers
// ---------------------------------------------------------------------------
__device__ __forceinline__ u64 ld_relaxed_gpu(const u64* p) {
    u64 v;
    asm volatile("ld.relaxed.gpu.b64 %0, [%1];" : "=l"(v) : "l"(p) : "memory");
    return v;
}
__device__ __forceinline__ void st_relaxed_gpu(u64* p, u64 v) {
    asm volatile("st.relaxed.gpu.b64 [%0], %1;" :: "l"(p), "l"(v) : "memory");
}
__device__ __forceinline__ u64 ffma2(u64 a, u64 b, u64 c) {
    u64 d;
    asm("fma.rn.f32x2 %0, %1, %2, %3;" : "=l"(d) : "l"(a), "l"(b), "l"(c));
    return d;
}
__device__ __forceinline__ u64 pack2(float lo, float hi) {
    u64 d;
    asm("mov.b64 %0, {%1, %2};" : "=l"(d) : "f"(lo), "f"(hi));
    return d;
}
__device__ __forceinline__ float2 unpack2(u64 v) {
    float lo, hi;
    asm("mov.b64 {%0, %1}, %2;" : "=f"(lo), "=f"(hi) : "l"(v));
    return make_float2(lo, hi);
}
__device__ __forceinline__ void bar_sync_named(int id, int cnt) {
    asm volatile("bar.sync %0, %1;" :: "r"(id), "r"(cnt) : "memory");
}
__device__ __forceinline__ void bar_arrive_named(int id, int cnt) {
    asm volatile("bar.arrive %0, %1;" :: "r"(id), "r"(cnt) : "memory");
}
// tanh via MUFU: 1 - 2/(exp(2x)+1). Saturates correctly for |x| large.
__device__ __forceinline__ float fast_tanh(float x) {
    return 1.f - __fdividef(2.f, __expf(2.f * x) + 1.f);
}

// ---------------------------------------------------------------------------
// Kernel 1: x_proj[t][gate][h] = b_gate[h] + sum_i x[63,t,i] * Wgate_x[i,h]
// ---------------------------------------------------------------------------
__global__ __launch_bounds__(256) void xproj_kernel(
    const float* __restrict__ x,
    const float* __restrict__ Wfx, const float* __restrict__ bf,
    const float* __restrict__ Wix, const float* __restrict__ bi,
    const float* __restrict__ Wgx, const float* __restrict__ bg,
    const float* __restrict__ Wox, const float* __restrict__ bo)
{
    __shared__ float xs[32][IDIM];   // 32 KB

    const float* x63 = x + (size_t)63 * T_STEPS * IDIM;
    const int tid    = threadIdx.x;
    const int cc     = blockIdx.x;             // 0..15
    const int tchunk = blockIdx.y;             // 0..31
    const int gate   = cc >> 2;                // f=0, i=1, g=2, o=3
    const int col    = ((cc & 3) << 8) + tid;  // h-column within gate

    const float* W;
    const float* b;
    if      (gate == 0) { W = Wfx; b = bf; }
    else if (gate == 1) { W = Wix; b = bi; }
    else if (gate == 2) { W = Wgx; b = bg; }
    else                { W = Wox; b = bo; }

    #pragma unroll 4
    for (int k = 0; k < 32; k++)
        xs[k][tid] = x63[(size_t)(tchunk * 32 + k) * IDIM + tid];
    __syncthreads();

    float acc[32];
    #pragma unroll
    for (int t = 0; t < 32; t++) acc[t] = 0.f;

    for (int i = 0; i < IDIM; i++) {
        float wv = __ldg(&W[(size_t)i * HDIM + col]);
        #pragma unroll
        for (int t = 0; t < 32; t++)
            acc[t] = fmaf(xs[t][i], wv, acc[t]);
    }

    const float bias = __ldg(&b[col]);
    #pragma unroll
    for (int t = 0; t < 32; t++)
        g_xproj[(size_t)(tchunk * 32 + t) * 4096 + gate * HDIM + col] = acc[t] + bias;
}

// ---------------------------------------------------------------------------
// Kernel 2: persistent recurrence, 1024 steps, tag-polling synchronization.
// Warps 1..16: warp w consumes h rows [64(w-1), 64w): unit-stride coalesced
//   dependent tag-poll (2 LDGs, 16 sectors), smem stage, 32 packed f32x2
//   FMAs against register-resident weight pairs, one partial, bar.arrive
//   (release -- orders the partial store for the reducer).
// Warp 0: prefetches xproj (hidden under bar wait), bar.sync, treed 16->1
//   reduce, sigmoid gates, cell update + fast tanh, publishes 8 tagged h.
// partial[] is single-buffered: producers cannot write step-(t+1) partials
// until warp 0 published h(t+1), which follows its step-t reduce.
// ---------------------------------------------------------------------------
__global__ __launch_bounds__(REC_THREADS, 1) void rec_kernel(
    const float* __restrict__ Wfh, const float* __restrict__ Wih,
    const float* __restrict__ Wgh, const float* __restrict__ Woh,
    const float* __restrict__ Wph, const float* __restrict__ bp,
    float* __restrict__ out)
{
    __shared__ __align__(16) float hs[16][64];   // per-producer-warp h slice
    __shared__ float partial[16][33];            // [producer][gate-col]

    const int tid  = threadIdx.x;
    const int w    = tid >> 5;
    const int lane = tid & 31;
    const int c    = blockIdx.x;

    const int gate = lane >> 3;
    const int hh   = lane & 7;
    const int hcol = c * 8 + hh;

    if (w == 0) {
        // ---------------- Reducer warp ----------------
        float Creg = 0.f;  // lanes 0..7 hold C for h-cols [8c, 8c+8)
        const float* xpp = &g_xproj[(size_t)gate * HDIM + hcol];

        for (int t = 0; t < T_STEPS; t++) {
            const float xp = __ldg(xpp + (size_t)t * 4096);  // hidden by bar wait
            bar_sync_named(1 + (t & 1), REC_THREADS);

            // Treed 16 -> 1 reduction of producer partials
            float p0 = partial[ 0][lane], p1 = partial[ 1][lane];
            float p2 = partial[ 2][lane], p3 = partial[ 3][lane];
            float p4 = partial[ 4][lane], p5 = partial[ 5][lane];
            float p6 = partial[ 6][lane], p7 = partial[ 7][lane];
            float p8 = partial[ 8][lane], p9 = partial[ 9][lane];
            float pa = partial[10][lane], pb = partial[11][lane];
            float pc = partial[12][lane], pd = partial[13][lane];
            float pe = partial[14][lane], pf = partial[15][lane];
            float s = (((p0 + p1) + (p2 + p3)) + ((p4 + p5) + (p6 + p7)))
                    + (((p8 + p9) + (pa + pb)) + ((pc + pd) + (pe + pf)))
                    + xp;

            // All four gates are sigmoid (per reference)
            const float sg = __fdividef(1.f, 1.f + __expf(-s));
            const float iv = __shfl_sync(0xffffffffu, sg,  8 + hh);
            const float gv = __shfl_sync(0xffffffffu, sg, 16 + hh);
            const float ov = __shfl_sync(0xffffffffu, sg, 24 + hh);
            if (lane < 8) {
                Creg = fmaf(Creg, sg, gv * iv);          // C = C*f + g*i
                const float hn = ov * fast_tanh(Creg);   // h = o*tanh(C)
                const u64 pk = ((u64)(unsigned)(t + 1) << 32)
                             | (u64)__float_as_uint(hn);
                st_relaxed_gpu(&g_hbuf[(t + 1) & (NBUF - 1)][hcol], pk);
            }
        }
    } else {
        // ---------------- Producer warps 1..16 ----------------
        const int pw = w - 1;                 // producer index 0..15
        const float* Wp = (gate == 0) ? Wfh : (gate == 1) ? Wih
                        : (gate == 2) ? Wgh : Woh;

        // Register-resident weight pairs for rows [64*pw, 64*pw+64)
        u64 W2[32];
        {
            const float* base = Wp + (size_t)(pw * 64) * HDIM + hcol;
            #pragma unroll
            for (int j = 0; j < 32; j++)
                W2[j] = pack2(base[(size_t)(2 * j) * HDIM],
                              base[(size_t)(2 * j + 1) * HDIM]);
        }

        const int base = pw * 64;             // this warp's h slice base

        for (int t = 0; t < T_STEPS; t++) {
            // Unit-stride coalesced dependent poll: lane l polls words
            // base+l and base+32+l (8 sectors per LDG). Single probe in
            // flight -- measured optimal (pipelined probes stack the L1tex
            // wavefront queue and regress).
            const u64* hin = g_hbuf[t & (NBUF - 1)] + base;
            const unsigned tg = (unsigned)t;
            u64 v0 = ld_relaxed_gpu(&hin[lane]);
            u64 v1 = ld_relaxed_gpu(&hin[lane + 32]);
            while ((unsigned)(v0 >> 32) != tg || (unsigned)(v1 >> 32) != tg) {
                v0 = ld_relaxed_gpu(&hin[lane]);
                v1 = ld_relaxed_gpu(&hin[lane + 32]);
            }
            hs[pw][lane]      = __uint_as_float((unsigned)v0);
            hs[pw][lane + 32] = __uint_as_float((unsigned)v1);
            __syncwarp();

            // GEMV partial: 64 rows x 1 gate-column, packed f32x2
            const ulonglong2* hp = reinterpret_cast<const ulonglong2*>(hs[pw]);
            u64 acc0 = 0, acc1 = 0, acc2 = 0, acc3 = 0;  // {0.f, 0.f} bits
            #pragma unroll
            for (int k = 0; k < 8; k++) {
                ulonglong2 ha = hp[2 * k];
                ulonglong2 hb = hp[2 * k + 1];
                acc0 = ffma2(W2[4 * k + 0], ha.x, acc0);
                acc1 = ffma2(W2[4 * k + 1], ha.y, acc1);
                acc2 = ffma2(W2[4 * k + 2], hb.x, acc2);
                acc3 = ffma2(W2[4 * k + 3], hb.y, acc3);
            }
            float2 f0 = unpack2(acc0), f1 = unpack2(acc1);
            float2 f2 = unpack2(acc2), f3 = unpack2(acc3);
            partial[pw][lane] =
                ((f0.x + f0.y) + (f1.x + f1.y)) + ((f2.x + f2.y) + (f3.x + f3.y));

            // bar.arrive has release semantics on the named barrier: the
            // partial[] store above is ordered before the reducer's loads
            // that follow its bar.sync. (No explicit MEMBAR needed.)
            bar_arrive_named(1 + (t & 1), REC_THREADS);  // non-blocking
        }
    }

    // Head: y[p] = bp[p] + sum_h h_final[h] * Wph[h][p]   (CTA 0 only)
    if (c == 0 && tid < 32 * PDIM) {
        const u64* hf = g_hbuf[T_STEPS & (NBUF - 1)];
        const int p = tid >> 5;
        float acc = 0.f;
        for (int k = lane; k < HDIM; k += 32) {
            u64 v = ld_relaxed_gpu(&hf[k]);
            while ((unsigned)(v >> 32) != (unsigned)T_STEPS)
                v = ld_relaxed_gpu(&hf[k]);
            acc = fmaf(__uint_as_float((unsigned)v),
                       __ldg(&Wph[(size_t)k * PDIM + p]), acc);
        }
        #pragma unroll
        for (int off = 16; off; off >>= 1)
            acc += __shfl_down_sync(0xffffffffu, acc, off);
        if (lane == 0) out[p] = acc + __ldg(&bp[p]);
    }
}

// ---------------------------------------------------------------------------
extern "C" void kernel_launch(void* const* d_in, const int* in_sizes, int n_in,
                              void* d_out, int out_size)
{
    const float* x   = (const float*)d_in[0];
    const float* Wfx = (const float*)d_in[1];
    const float* Wfh = (const float*)d_in[2];
    const float* bf  = (const float*)d_in[3];
    const float* Wix = (const float*)d_in[4];
    const float* Wih = (const float*)d_in[5];
    const float* bi  = (const float*)d_in[6];
    const float* Wgx = (const float*)d_in[7];
    const float* Wgh = (const float*)d_in[8];
    const float* bg  = (const float*)d_in[9];
    const float* Wox = (const float*)d_in[10];
    const float* Woh = (const float*)d_in[11];
    const float* bo  = (const float*)d_in[12];
    const float* Wph = (const float*)d_in[13];
    const float* bp  = (const float*)d_in[14];
    float* out = (float*)d_out;

    // Tag 0 == "h^0 ready, value 0" -- zeroing IS the initial state.
    void* d_h = nullptr;
    cudaGetSymbolAddress(&d_h, g_hbuf);
    cudaMemsetAsync(d_h, 0, NBUF * HDIM * sizeof(u64));

    xproj_kernel<<<dim3(16, 32), 256>>>(x, Wfx, bf, Wix, bi, Wgx, bg, Wox, bo);
    rec_kernel<<<REC_CTAS, REC_THREADS>>>(Wfh, Wih, Wgh, Woh, Wph, bp, out);
}